// round 16
// baseline (speedup 1.0000x reference)
#include <cuda_runtime.h>
#include <cuda_fp16.h>
#include <math.h>

#define BB 8
#define SS 4096
#define DD 768
#define MM 64
#define FF 3072
#define HH 12
#define HD 64
#define EPSF 1e-5f

typedef unsigned long long ull;

__device__ __forceinline__ ull pk2(float lo, float hi) {
    ull r;
    asm("mov.b64 %0, {%1, %2};" : "=l"(r) : "f"(lo), "f"(hi));
    return r;
}
__device__ __forceinline__ void upk2(ull v, float& lo, float& hi) {
    asm("mov.b64 {%0, %1}, %2;" : "=f"(lo), "=f"(hi) : "l"(v));
}
#define FMA2(a, x, y) asm("fma.rn.f32x2 %0, %1, %2, %0;" : "+l"(a) : "l"(x), "l"(y))

__device__ __forceinline__ unsigned su32(const void* p) {
    return (unsigned)__cvta_generic_to_shared(p);
}
__device__ __forceinline__ void cpasync16(unsigned dst, const void* src) {
    asm volatile("cp.async.cg.shared.global [%0], [%1], 16;" :: "r"(dst), "l"(src));
}

#define MMA16816(c, A, b0, b1) \
    asm volatile("mma.sync.aligned.m16n8k16.row.col.f32.f16.f16.f32 " \
        "{%0,%1,%2,%3}, {%4,%5,%6,%7}, {%8,%9}, {%0,%1,%2,%3};" \
        : "+f"((c)[0]), "+f"((c)[1]), "+f"((c)[2]), "+f"((c)[3]) \
        : "r"((A)[0]), "r"((A)[1]), "r"((A)[2]), "r"((A)[3]), "r"(b0), "r"(b1))

// ---------------- scratch -----------------------------------------------------
__device__ __half g_slh[MM * DD];
__device__ __half g_nh[BB * SS * DD];
__device__ float  g_tn[BB * SS];
__device__ __half g_lh[(size_t)BB * HH * MM * SS];
__device__ float  g_bmax[MM];
__device__ float  g_rsum[BB * HH * MM];
__device__ float  g_y[BB * MM * DD];
__device__ float  g_hid[(size_t)BB * MM * FF];
__device__ float  g_y2[BB * MM * DD];

// ---------------- K0: slots (fp16 out) + bmax + zero rsum -------------------------
__global__ void k_slots(const float* __restrict__ slots, const float* __restrict__ scale) {
    int m = blockIdx.x, tid = threadIdx.x;
    __shared__ float red[8];
    float ss = 0.f;
    for (int i = tid; i < DD; i += 256) { float v = slots[m * DD + i]; ss += v * v; }
    for (int o = 16; o; o >>= 1) ss += __shfl_down_sync(~0u, ss, o);
    if ((tid & 31) == 0) red[tid >> 5] = ss;
    __syncthreads();
    if (tid == 0) { float s = 0; for (int i = 0; i < 8; i++) s += red[i]; red[0] = s; }
    __syncthreads();
    float inv = scale[m] / fmaxf(sqrtf(red[0]), EPSF);
    for (int i = tid; i < DD; i += 256) g_slh[m * DD + i] = __float2half(slots[m * DD + i] * inv);
    if (tid == 0) g_bmax[m] = fabsf(scale[m]);
    int i = m * 256 + tid;
    if (i < BB * HH * MM) g_rsum[i] = 0.f;
}

// ---------------- K1: rmsnorm -> nh fp16 + token norm ----------------------------
__global__ void k_norm(const float* __restrict__ x, const float* __restrict__ nw) {
    int t = blockIdx.x, tid = threadIdx.x;
    __shared__ float red[6];
    __shared__ float bval, bval2;
    float4 v = ((const float4*)(x + (size_t)t * DD))[tid];
    float ss = v.x * v.x + v.y * v.y + v.z * v.z + v.w * v.w;
    for (int o = 16; o; o >>= 1) ss += __shfl_down_sync(~0u, ss, o);
    if ((tid & 31) == 0) red[tid >> 5] = ss;
    __syncthreads();
    if (tid == 0) {
        float s = 0; for (int i = 0; i < 6; i++) s += red[i];
        bval = rsqrtf(s / (float)DD + EPSF);
    }
    __syncthreads();
    float rstd = bval;
    float4 w = ((const float4*)nw)[tid];
    float4 a;
    a.x = v.x * rstd * w.x; a.y = v.y * rstd * w.y;
    a.z = v.z * rstd * w.z; a.w = v.w * rstd * w.w;
    float s2 = a.x * a.x + a.y * a.y + a.z * a.z + a.w * a.w;
    for (int o = 16; o; o >>= 1) s2 += __shfl_down_sync(~0u, s2, o);
    if ((tid & 31) == 0) red[tid >> 5] = s2;
    __syncthreads();
    if (tid == 0) {
        float s = 0; for (int i = 0; i < 6; i++) s += red[i];
        float tnv = fmaxf(sqrtf(s), EPSF);
        g_tn[t] = tnv;
        bval2 = 1.f / tnv;
    }
    __syncthreads();
    float rn = bval2;
    __half2 h0 = __float22half2_rn(make_float2(a.x * rn, a.y * rn));
    __half2 h1 = __float22half2_rn(make_float2(a.z * rn, a.w * rn));
    uint2 u;
    u.x = *(unsigned*)&h0; u.y = *(unsigned*)&h1;
    *(uint2*)(g_nh + (size_t)t * DD + tid * 4) = u;
}

// ---------------- K2: binit (float4) -----------------------------------------------
__global__ void k_binit(const float* __restrict__ b1, const float* __restrict__ b2) {
    int i4 = (blockIdx.x * 256 + threadIdx.x) * 4;
    const int N1 = BB * MM * DD;
    const int N2 = BB * MM * FF;
    if (i4 < N1) *(float4*)&g_y[i4] = make_float4(0.f, 0.f, 0.f, 0.f);
    else if (i4 < N1 + N2) {
        int k = i4 - N1;
        *(float4*)&g_hid[k] = *(const float4*)&b1[k % (MM * FF)];
    } else {
        int k = i4 - N1 - N2;
        *(float4*)&g_y2[k] = *(const float4*)&b2[k % (MM * DD)];
    }
}

// ---------------- K3: logits via mma + fused row sums (idx 3 profiled) --------------
__global__ void __launch_bounds__(128) k_logits() {
    int s0 = blockIdx.x * 128;
    int h = blockIdx.y, b = blockIdx.z;
    int tid = threadIdx.x, lane = tid & 31, wid = tid >> 5;
    __shared__ __half As[64][72];
    __shared__ __half Bs[128][72];          // reused as Cs after Bf loads
    __shared__ float bmS[64];
    __shared__ float wsum[4][64];
    __half (*Cs)[136] = (__half(*)[136])&Bs[0][0];
    for (int i = tid; i < 64 * 8; i += 128) {
        int r = i >> 3, sg = i & 7;
        *(uint4*)&As[r][sg * 8] = *(const uint4*)&g_slh[r * DD + h * HD + sg * 8];
    }
    for (int i = tid; i < 128 * 8; i += 128) {
        int r = i >> 3, sg = i & 7;
        *(uint4*)&Bs[r][sg * 8] =
            *(const uint4*)&g_nh[((size_t)(b * SS + s0 + r)) * DD + h * HD + sg * 8];
    }
    if (tid < 64) bmS[tid] = g_bmax[tid];
    __syncthreads();
    int nb = wid * 32;
    unsigned Bf[4][4][2];
#pragma unroll
    for (int j = 0; j < 4; j++)
#pragma unroll
        for (int kk = 0; kk < 4; kk++) {
            unsigned ad = su32(&Bs[nb + j * 8 + (lane & 7)][kk * 16 + (lane & 8)]);
            asm volatile("ldmatrix.sync.aligned.m8n8.x2.shared.b16 {%0,%1}, [%2];"
                : "=r"(Bf[j][kk][0]), "=r"(Bf[j][kk][1]) : "r"(ad));
        }
    __syncthreads();
    float rs[4], rs8[4];
#pragma unroll
    for (int mi = 0; mi < 4; mi++) { rs[mi] = 0.f; rs8[mi] = 0.f; }
#pragma unroll
    for (int mi = 0; mi < 4; mi++) {
        unsigned Af[4][4];
#pragma unroll
        for (int kk = 0; kk < 4; kk++) {
            unsigned ad = su32(&As[mi * 16 + (lane & 15)][kk * 16 + ((lane & 16) >> 1)]);
            asm volatile("ldmatrix.sync.aligned.m8n8.x4.shared.b16 {%0,%1,%2,%3}, [%4];"
                : "=r"(Af[kk][0]), "=r"(Af[kk][1]), "=r"(Af[kk][2]), "=r"(Af[kk][3])
                : "r"(ad));
        }
        float bm0 = bmS[mi * 16 + (lane >> 2)];
        float bm1 = bmS[mi * 16 + 8 + (lane >> 2)];
#pragma unroll
        for (int j = 0; j < 4; j++) {
            float c[4] = {0.f, 0.f, 0.f, 0.f};
#pragma unroll
            for (int kk = 0; kk < 4; kk++)
                MMA16816(c, Af[kk], Bf[j][kk][0], Bf[j][kk][1]);
            int m = mi * 16 + (lane >> 2);
            int n = nb + j * 8 + 2 * (lane & 3);
            *(__half2*)&Cs[m][n]     = __float22half2_rn(make_float2(c[0], c[1]));
            *(__half2*)&Cs[m + 8][n] = __float22half2_rn(make_float2(c[2], c[3]));
            rs[mi]  += __expf(c[0] - bm0) + __expf(c[1] - bm0);
            rs8[mi] += __expf(c[2] - bm1) + __expf(c[3] - bm1);
        }
    }
#pragma unroll
    for (int mi = 0; mi < 4; mi++) {
        rs[mi]  += __shfl_xor_sync(~0u, rs[mi], 1);
        rs[mi]  += __shfl_xor_sync(~0u, rs[mi], 2);
        rs8[mi] += __shfl_xor_sync(~0u, rs8[mi], 1);
        rs8[mi] += __shfl_xor_sync(~0u, rs8[mi], 2);
        if ((lane & 3) == 0) {
            wsum[wid][mi * 16 + (lane >> 2)]     = rs[mi];
            wsum[wid][mi * 16 + 8 + (lane >> 2)] = rs8[mi];
        }
    }
    __syncthreads();
    if (tid < 64) {
        float tot = wsum[0][tid] + wsum[1][tid] + wsum[2][tid] + wsum[3][tid];
        atomicAdd(&g_rsum[(b * HH + h) * MM + tid], tot);
    }
    size_t lbase = (size_t)((b * HH + h) * MM) * SS + s0;
    for (int u = tid; u < 64 * 16; u += 128) {
        int m = u >> 4, q = u & 15;
        *(uint4*)&g_lh[lbase + (size_t)m * SS + q * 8] = *(const uint4*)&Cs[m][q * 8];
    }
}

// ---------------- K4: dispatch via mma (bmax shift) ---------------------------------
__global__ void __launch_bounds__(128) k_disp() {
    int ch = blockIdx.x, h = blockIdx.y, b = blockIdx.z;
    int tid = threadIdx.x, lane = tid & 31, wid = tid >> 5;
    __shared__ __half As[64][72];
    __shared__ __half Bs[64][72];
    __shared__ float smax[64], sinv[64], tns[512];
    if (tid < 64) {
        smax[tid] = g_bmax[tid];
        sinv[tid] = 1.f / g_rsum[(b * HH + h) * MM + tid];
    }
    for (int u = tid; u < 512; u += 128) tns[u] = g_tn[b * SS + ch * 512 + u];
    float acc[4][2][4];
#pragma unroll
    for (int i = 0; i < 4; i++)
#pragma unroll
        for (int j = 0; j < 2; j++)
#pragma unroll
            for (int q = 0; q < 4; q++) acc[i][j][q] = 0.f;
    size_t lbh = (size_t)((b * HH + h) * MM) * SS;
    int nb = wid * 16;
    __syncthreads();
    for (int tile = 0; tile < 8; tile++) {
        int s0 = ch * 512 + tile * 64;
        if (tile) __syncthreads();
        for (int u = tid; u < 512; u += 128) {
            int m = u >> 3, q = u & 7;
            uint4 raw = *(const uint4*)&g_lh[lbh + (size_t)m * SS + s0 + q * 8];
            const __half2* h2 = (const __half2*)&raw;
            float mm = smax[m], iv = sinv[m];
            const float* tp = &tns[tile * 64 + q * 8];
            __half2 outh[4];
#pragma unroll
            for (int j = 0; j < 4; j++) {
                float2 f = __half22float2(h2[j]);
                float e0 = __expf(f.x - mm) * iv * tp[2 * j];
                float e1 = __expf(f.y - mm) * iv * tp[2 * j + 1];
                outh[j] = __float22half2_rn(make_float2(e0, e1));
            }
            *(uint4*)&As[m][q * 8] = *(uint4*)outh;
        }
        for (int u = tid; u < 512; u += 128) {
            int s = u >> 3, q = u & 7;
            *(uint4*)&Bs[s][q * 8] =
                *(const uint4*)&g_nh[((size_t)(b * SS + s0 + s)) * DD + h * HD + q * 8];
        }
        __syncthreads();
#pragma unroll
        for (int kk = 0; kk < 4; kk++) {
            unsigned Af[4][4];
#pragma unroll
            for (int mi = 0; mi < 4; mi++) {
                unsigned ad = su32(&As[mi * 16 + (lane & 15)][kk * 16 + ((lane & 16) >> 1)]);
                asm volatile("ldmatrix.sync.aligned.m8n8.x4.shared.b16 {%0,%1,%2,%3}, [%4];"
                    : "=r"(Af[mi][0]), "=r"(Af[mi][1]), "=r"(Af[mi][2]), "=r"(Af[mi][3])
                    : "r"(ad));
            }
            unsigned Bf[4];
            {
                unsigned ad = su32(&Bs[kk * 16 + ((lane >> 3) & 1) * 8 + (lane & 7)]
                                     [nb + ((lane >> 4) & 1) * 8]);
                asm volatile("ldmatrix.sync.aligned.m8n8.x4.trans.shared.b16 {%0,%1,%2,%3}, [%4];"
                    : "=r"(Bf[0]), "=r"(Bf[1]), "=r"(Bf[2]), "=r"(Bf[3]) : "r"(ad));
            }
#pragma unroll
            for (int mi = 0; mi < 4; mi++) {
                MMA16816(acc[mi][0], Af[mi], Bf[0], Bf[1]);
                MMA16816(acc[mi][1], Af[mi], Bf[2], Bf[3]);
            }
        }
    }
#pragma unroll
    for (int mi = 0; mi < 4; mi++) {
        int m = mi * 16 + (lane >> 2);
#pragma unroll
        for (int nj = 0; nj < 2; nj++) {
            int d = nb + nj * 8 + 2 * (lane & 3);
            float* bp = &g_y[((size_t)(b * MM + m)) * DD + h * HD + d];
            atomicAdd(bp, acc[mi][nj][0]);
            atomicAdd(bp + 1, acc[mi][nj][1]);
            atomicAdd(bp + 8 * DD, acc[mi][nj][2]);
            atomicAdd(bp + 8 * DD + 1, acc[mi][nj][3]);
        }
    }
}

// ---------------- K5: fc1 (3-stage x 4-row cp.async ring, proven) --------------------
__global__ void __launch_bounds__(256) k_fc1(const float* __restrict__ w1) {
    int fblk = blockIdx.x, m = blockIdx.y, kc = blockIdx.z;
    int tid = threadIdx.x;
    int f = fblk * 1024 + tid * 4;
    __shared__ float ysT[128][12];
    __shared__ float wbuf[3][4][1024];
    for (int i = tid; i < 8 * 128; i += 256) {
        int bb = i >> 7, k = i & 127;
        ysT[k][bb] = g_y[((size_t)(bb * MM + m)) * DD + kc * 128 + k];
    }
    __syncthreads();
    const float* wp = w1 + (size_t)m * DD * FF + (size_t)(kc * 128) * FF + f;
    const int NS = 32;
#pragma unroll
    for (int s = 0; s < 2; s++) {
#pragma unroll
        for (int j = 0; j < 4; j++)
            cpasync16(su32(&wbuf[s][j][tid * 4]), wp + (size_t)(s * 4 + j) * FF);
        asm volatile("cp.async.commit_group;");
    }
    ull acc[4][4];
#pragma unroll
    for (int i = 0; i < 4; i++)
#pragma unroll
        for (int j = 0; j < 4; j++) acc[i][j] = 0ull;
    int nxt = 2;
    for (int s = 0; s < NS; s++) {
        int buf = s % 3;
        if (s + 2 < NS) {
            int nb2 = nxt; nxt = (nxt + 1) % 3;
#pragma unroll
            for (int j = 0; j < 4; j++)
                cpasync16(su32(&wbuf[nb2][j][tid * 4]), wp + (size_t)((s + 2) * 4 + j) * FF);
            asm volatile("cp.async.commit_group;");
            asm volatile("cp.async.wait_group 2;");
        } else if (s + 1 < NS) {
            asm volatile("cp.async.wait_group 1;");
        } else {
            asm volatile("cp.async.wait_group 0;");
        }
#pragma unroll
        for (int j = 0; j < 4; j++) {
            int k = s * 4 + j;
            float4 wv = *(const float4*)&wbuf[buf][j][tid * 4];
            ulonglong2 ya = *(const ulonglong2*)&ysT[k][0];
            ulonglong2 yb = *(const ulonglong2*)&ysT[k][4];
            ull d0 = pk2(wv.x, wv.x), d1 = pk2(wv.y, wv.y);
            ull d2 = pk2(wv.z, wv.z), d3 = pk2(wv.w, wv.w);
            FMA2(acc[0][0], d0, ya.x); FMA2(acc[0][1], d0, ya.y); FMA2(acc[0][2], d0, yb.x); FMA2(acc[0][3], d0, yb.y);
            FMA2(acc[1][0], d1, ya.x); FMA2(acc[1][1], d1, ya.y); FMA2(acc[1][2], d1, yb.x); FMA2(acc[1][3], d1, yb.y);
            FMA2(acc[2][0], d2, ya.x); FMA2(acc[2][1], d2, ya.y); FMA2(acc[2][2], d2, yb.x); FMA2(acc[2][3], d2, yb.y);
            FMA2(acc[3][0], d3, ya.x); FMA2(acc[3][1], d3, ya.y); FMA2(acc[3][2], d3, yb.x); FMA2(acc[3][3], d3, yb.y);
        }
    }
#pragma unroll
    for (int fi = 0; fi < 4; fi++)
#pragma unroll
        for (int bp = 0; bp < 4; bp++) {
            float a0, a1;
            upk2(acc[fi][bp], a0, a1);
            atomicAdd(&g_hid[((size_t)((2 * bp) * MM + m)) * FF + f + fi], a0);
            atomicAdd(&g_hid[((size_t)((2 * bp + 1) * MM + m)) * FF + f + fi], a1);
        }
}

// ---------------- K6: fc2 (gelu on load; 3-stage x 4-row cp.async ring, proven) ------
__global__ void __launch_bounds__(192) k_fc2(const float* __restrict__ w2) {
    int m = blockIdx.x, kc = blockIdx.y;
    int tid = threadIdx.x;
    int d = tid * 4;
    __shared__ float hsT[192][12];
    __shared__ float wbuf[3][4][768];
    for (int i = tid; i < 8 * 192; i += 192) {
        int bb = i / 192, k = i % 192;
        float v = g_hid[((size_t)(bb * MM + m)) * FF + kc * 192 + k];
        hsT[k][bb] = 0.5f * v * (1.f + erff(v * 0.70710678118654752f));
    }
    __syncthreads();
    const float* wp = w2 + (size_t)m * FF * DD + (size_t)(kc * 192) * DD + d;
    const int NS = 48;
#pragma unroll
    for (int s = 0; s < 2; s++) {
#pragma unroll
        for (int j = 0; j < 4; j++)
            cpasync16(su32(&wbuf[s][j][tid * 4]), wp + (size_t)(s * 4 + j) * DD);
        asm volatile("cp.async.commit_group;");
    }
    ull acc[4][4];
#pragma unroll
    for (int i = 0; i < 4; i++)
#pragma unroll
        for (int j = 0; j < 4; j++) acc[i][j] = 0ull;
    int nxt = 2;
    for (int s = 0; s < NS; s++) {
        int buf = s % 3;
        if (s + 2 < NS) {
            int nb2 = nxt; nxt = (nxt + 1) % 3;
#pragma unroll
            for (int j = 0; j < 4; j++)
                cpasync16(su32(&wbuf[nb2][j][tid * 4]), wp + (size_t)((s + 2) * 4 + j) * DD);
            asm volatile("cp.async.commit_group;");
            asm volatile("cp.async.wait_group 2;");
        } else if (s + 1 < NS) {
            asm volatile("cp.async.wait_group 1;");
        } else {
            asm volatile("cp.async.wait_group 0;");
        }
#pragma unroll
        for (int j = 0; j < 4; j++) {
            int k = s * 4 + j;
            float4 wv = *(const float4*)&wbuf[buf][j][tid * 4];
            ulonglong2 ya = *(const ulonglong2*)&hsT[k][0];
            ulonglong2 yb = *(const ulonglong2*)&hsT[k][4];
            ull d0 = pk2(wv.x, wv.x), d1 = pk2(wv.y, wv.y);
            ull d2 = pk2(wv.z, wv.z), d3 = pk2(wv.w, wv.w);
            FMA2(acc[0][0], d0, ya.x); FMA2(acc[0][1], d0, ya.y); FMA2(acc[0][2], d0, yb.x); FMA2(acc[0][3], d0, yb.y);
            FMA2(acc[1][0], d1, ya.x); FMA2(acc[1][1], d1, ya.y); FMA2(acc[1][2], d1, yb.x); FMA2(acc[1][3], d1, yb.y);
            FMA2(acc[2][0], d2, ya.x); FMA2(acc[2][1], d2, ya.y); FMA2(acc[2][2], d2, yb.x); FMA2(acc[2][3], d2, yb.y);
            FMA2(acc[3][0], d3, ya.x); FMA2(acc[3][1], d3, ya.y); FMA2(acc[3][2], d3, yb.x); FMA2(acc[3][3], d3, yb.y);
        }
    }
#pragma unroll
    for (int di = 0; di < 4; di++)
#pragma unroll
        for (int bp = 0; bp < 4; bp++) {
            float a0, a1;
            upk2(acc[di][bp], a0, a1);
            atomicAdd(&g_y2[((size_t)((2 * bp) * MM + m)) * DD + d + di], a0);
            atomicAdd(&g_y2[((size_t)((2 * bp + 1) * MM + m)) * DD + d + di], a1);
        }
}

// ---------------- K7: combine via mma -----------------------------------------------
__global__ void __launch_bounds__(128) k_comb(float* __restrict__ out) {
    int sb = blockIdx.x, h = blockIdx.y, b = blockIdx.z;
    int s0 = sb * 128;
    int tid = threadIdx.x, lane = tid & 31, w = tid >> 5;
    __shared__ __half As[64][136];
    __shared__ __half Bs[64][72];
    __shared__ float sinvs[128];
    size_t lbh = (size_t)((b * HH + h) * MM) * SS;
    for (int u = tid; u < 1024; u += 128) {
        int m = u >> 4, q = u & 15;
        *(uint4*)&As[m][q * 8] = *(const uint4*)&g_lh[lbh + (size_t)m * SS + s0 + q * 8];
    }
    for (int u = tid; u < 1024; u += 128) {
        int m = u >> 4, q = u & 15;
        float4 v = *(const float4*)&g_y2[((size_t)(b * MM + m)) * DD + h * HD + q * 4];
        __half2 h0 = __float22half2_rn(make_float2(v.x, v.y));
        __half2 h1 = __float22half2_rn(make_float2(v.z, v.w));
        uint2 st;
        st.x = *(unsigned*)&h0; st.y = *(unsigned*)&h1;
        *(uint2*)&Bs[m][q * 4] = st;
    }
    __syncthreads();
    {
        float vals[64];
        float mx = -1e30f;
#pragma unroll
        for (int m = 0; m < 64; m++) {
            vals[m] = __half2float(As[m][tid]);
            mx = fmaxf(mx, vals[m]);
        }
        float sm = 0.f;
#pragma unroll
        for (int m = 0; m < 64; m++) {
            float e = __expf(vals[m] - mx);
            sm += e;
            As[m][tid] = __float2half(e);
        }
        sinvs[tid] = 1.f / sm;
    }
    __syncthreads();
    float acc[2][8][4];
#pragma unroll
    for (int i = 0; i < 2; i++)
#pragma unroll
        for (int j = 0; j < 8; j++)
#pragma unroll
            for (int q = 0; q < 4; q++) acc[i][j][q] = 0.f;
#pragma unroll
    for (int kk = 0; kk < 4; kk++) {
        unsigned Af[2][4];
#pragma unroll
        for (int mi2 = 0; mi2 < 2; mi2++) {
            int M0 = w * 32 + mi2 * 16;
            unsigned ad = su32(&As[kk * 16 + ((lane >> 4) & 1) * 8 + (lane & 7)]
                                 [M0 + ((lane >> 3) & 1) * 8]);
            asm volatile("ldmatrix.sync.aligned.m8n8.x4.trans.shared.b16 {%0,%1,%2,%3}, [%4];"
                : "=r"(Af[mi2][0]), "=r"(Af[mi2][1]), "=r"(Af[mi2][2]), "=r"(Af[mi2][3])
                : "r"(ad));
        }
        unsigned Bf[4][4];
#pragma unroll
        for (int p = 0; p < 4; p++) {
            unsigned ad = su32(&Bs[kk * 16 + ((lane >> 3) & 1) * 8 + (lane & 7)]
                                 [p * 16 + ((lane >> 4) & 1) * 8]);
            asm volatile("ldmatrix.sync.aligned.m8n8.x4.trans.shared.b16 {%0,%1,%2,%3}, [%4];"
                : "=r"(Bf[p][0]), "=r"(Bf[p][1]), "=r"(Bf[p][2]), "=r"(Bf[p][3])
                : "r"(ad));
        }
#pragma unroll
        for (int mi2 = 0; mi2 < 2; mi2++)
#pragma unroll
            for (int nj = 0; nj < 8; nj++)
                MMA16816(acc[mi2][nj], Af[mi2], Bf[nj >> 1][(nj & 1) * 2], Bf[nj >> 1][(nj & 1) * 2 + 1]);
    }
#pragma unroll
    for (int mi2 = 0; mi2 < 2; mi2++) {
        int srow = w * 32 + mi2 * 16 + (lane >> 2);
        float inv0 = sinvs[srow], inv1 = sinvs[srow + 8];
        float* o0 = &out[((size_t)(b * SS + s0 + srow)) * DD + h * HD];
        float* o1 = o0 + (size_t)8 * DD;
#pragma unroll
        for (int nj = 0; nj < 8; nj++) {
            int d = nj * 8 + 2 * (lane & 3);
            float2 v0 = make_float2(acc[mi2][nj][0] * inv0, acc[mi2][nj][1] * inv0);
            float2 v1 = make_float2(acc[mi2][nj][2] * inv1, acc[mi2][nj][3] * inv1);
            *(float2*)&o0[d] = v0;
            *(float2*)&o1[d] = v1;
        }
    }
}

// ---------------- launch --------------------------------------------------------
extern "C" void kernel_launch(void* const* d_in, const int* in_sizes, int n_in,
                              void* d_out, int out_size) {
    const float* x      = (const float*)d_in[0];
    const float* slots  = (const float*)d_in[1];
    const float* scale  = (const float*)d_in[2];
    const float* fc1_w  = (const float*)d_in[3];
    const float* fc1_b  = (const float*)d_in[4];
    const float* fc2_w  = (const float*)d_in[5];
    const float* fc2_b  = (const float*)d_in[6];
    const float* norm_w = (const float*)d_in[7];
    float* out = (float*)d_out;

    k_slots<<<MM, 256>>>(slots, scale);                                    // idx 0
    k_norm<<<BB * SS, 192>>>(x, norm_w);                                   // idx 1
    k_binit<<<(BB * MM * (2 * DD + FF)) / 1024, 256>>>(fc1_b, fc2_b);      // idx 2
    k_logits<<<dim3(SS / 128, HH, BB), 128>>>();                           // idx 3 (profiled)
    k_disp<<<dim3(8, HH, BB), 128>>>();                                    // idx 4
    k_fc1<<<dim3(3, MM, 6), 256>>>(fc1_w);                                 // idx 5
    k_fc2<<<dim3(MM, 16), 192>>>(fc2_w);                                   // idx 6
    k_comb<<<dim3(SS / 128, HH, BB), 128>>>(out);                          // idx 7
}

// round 17
// speedup vs baseline: 1.0480x; 1.0480x over previous
#include <cuda_runtime.h>
#include <cuda_fp16.h>
#include <math.h>

#define BB 8
#define SS 4096
#define DD 768
#define MM 64
#define FF 3072
#define HH 12
#define HD 64
#define EPSF 1e-5f

typedef unsigned long long ull;

__device__ __forceinline__ ull pk2(float lo, float hi) {
    ull r;
    asm("mov.b64 %0, {%1, %2};" : "=l"(r) : "f"(lo), "f"(hi));
    return r;
}
__device__ __forceinline__ void upk2(ull v, float& lo, float& hi) {
    asm("mov.b64 {%0, %1}, %2;" : "=f"(lo), "=f"(hi) : "l"(v));
}
#define FMA2(a, x, y) asm("fma.rn.f32x2 %0, %1, %2, %0;" : "+l"(a) : "l"(x), "l"(y))

__device__ __forceinline__ unsigned su32(const void* p) {
    return (unsigned)__cvta_generic_to_shared(p);
}
__device__ __forceinline__ void cpasync16(unsigned dst, const void* src) {
    asm volatile("cp.async.cg.shared.global [%0], [%1], 16;" :: "r"(dst), "l"(src));
}

#define MMA16816(c, A, b0, b1) \
    asm volatile("mma.sync.aligned.m16n8k16.row.col.f32.f16.f16.f32 " \
        "{%0,%1,%2,%3}, {%4,%5,%6,%7}, {%8,%9}, {%0,%1,%2,%3};" \
        : "+f"((c)[0]), "+f"((c)[1]), "+f"((c)[2]), "+f"((c)[3]) \
        : "r"((A)[0]), "r"((A)[1]), "r"((A)[2]), "r"((A)[3]), "r"(b0), "r"(b1))

// ---------------- scratch -----------------------------------------------------
__device__ __half g_slh[MM * DD];
__device__ __half g_nh[BB * SS * DD];
__device__ float  g_tn[BB * SS];
__device__ __half g_lh[(size_t)BB * HH * MM * SS];
__device__ float  g_rmax[BB * HH * MM];
__device__ float  g_rsum[BB * HH * MM];
__device__ float  g_y[BB * MM * DD];
__device__ float  g_hid[(size_t)BB * MM * FF];
__device__ float  g_y2[BB * MM * DD];

// ---------------- K0: slots (fp16 out) ------------------------------------------
__global__ void k_slots(const float* __restrict__ slots, const float* __restrict__ scale) {
    int m = blockIdx.x, tid = threadIdx.x;
    __shared__ float red[8];
    float ss = 0.f;
    for (int i = tid; i < DD; i += 256) { float v = slots[m * DD + i]; ss += v * v; }
    for (int o = 16; o; o >>= 1) ss += __shfl_down_sync(~0u, ss, o);
    if ((tid & 31) == 0) red[tid >> 5] = ss;
    __syncthreads();
    if (tid == 0) { float s = 0; for (int i = 0; i < 8; i++) s += red[i]; red[0] = s; }
    __syncthreads();
    float inv = scale[m] / fmaxf(sqrtf(red[0]), EPSF);
    for (int i = tid; i < DD; i += 256) g_slh[m * DD + i] = __float2half(slots[m * DD + i] * inv);
}

// ---------------- K1: rmsnorm, warp-per-token, shuffle-only ----------------------
__global__ void __launch_bounds__(256) k_norm(const float* __restrict__ x,
                                              const float* __restrict__ nw) {
    int t = blockIdx.x * 8 + (threadIdx.x >> 5);
    int lane = threadIdx.x & 31;
    const float4* xr = (const float4*)(x + (size_t)t * DD);
    const float4* wr = (const float4*)nw;
    float4 v[6];
    float ss = 0.f;
#pragma unroll
    for (int j = 0; j < 6; j++) {
        v[j] = xr[lane + 32 * j];
        ss += v[j].x * v[j].x + v[j].y * v[j].y + v[j].z * v[j].z + v[j].w * v[j].w;
    }
#pragma unroll
    for (int o = 16; o; o >>= 1) ss += __shfl_xor_sync(~0u, ss, o);
    float rstd = rsqrtf(ss / (float)DD + EPSF);
    float s2 = 0.f;
#pragma unroll
    for (int j = 0; j < 6; j++) {
        float4 w = wr[lane + 32 * j];
        v[j].x *= rstd * w.x; v[j].y *= rstd * w.y;
        v[j].z *= rstd * w.z; v[j].w *= rstd * w.w;
        s2 += v[j].x * v[j].x + v[j].y * v[j].y + v[j].z * v[j].z + v[j].w * v[j].w;
    }
#pragma unroll
    for (int o = 16; o; o >>= 1) s2 += __shfl_xor_sync(~0u, s2, o);
    float tnv = fmaxf(sqrtf(s2), EPSF);
    if (lane == 0) g_tn[t] = tnv;
    float rn = 1.f / tnv;
    __half* xo = g_nh + (size_t)t * DD;
#pragma unroll
    for (int j = 0; j < 6; j++) {
        __half2 h0 = __float22half2_rn(make_float2(v[j].x * rn, v[j].y * rn));
        __half2 h1 = __float22half2_rn(make_float2(v[j].z * rn, v[j].w * rn));
        uint2 u;
        u.x = *(unsigned*)&h0; u.y = *(unsigned*)&h1;
        *(uint2*)(xo + (lane + 32 * j) * 4) = u;
    }
}

// ---------------- K2: binit (float4) -----------------------------------------------
__global__ void k_binit(const float* __restrict__ b1, const float* __restrict__ b2) {
    int i4 = (blockIdx.x * 256 + threadIdx.x) * 4;
    const int N1 = BB * MM * DD;
    const int N2 = BB * MM * FF;
    if (i4 < N1) *(float4*)&g_y[i4] = make_float4(0.f, 0.f, 0.f, 0.f);
    else if (i4 < N1 + N2) {
        int k = i4 - N1;
        *(float4*)&g_hid[k] = *(const float4*)&b1[k % (MM * FF)];
    } else {
        int k = i4 - N1 - N2;
        *(float4*)&g_y2[k] = *(const float4*)&b2[k % (MM * DD)];
    }
}

// ---------------- K3: logits via mma, smem-staged coalesced store (idx 3) ---------
__global__ void __launch_bounds__(128) k_logits() {
    int s0 = blockIdx.x * 128;
    int h = blockIdx.y, b = blockIdx.z;
    int tid = threadIdx.x, lane = tid & 31, wid = tid >> 5;
    __shared__ __half As[64][72];
    __shared__ __half Bs[128][72];          // reused as Cs after Bf loads
    __half (*Cs)[136] = (__half(*)[136])&Bs[0][0];
    for (int i = tid; i < 64 * 8; i += 128) {
        int r = i >> 3, sg = i & 7;
        *(uint4*)&As[r][sg * 8] = *(const uint4*)&g_slh[r * DD + h * HD + sg * 8];
    }
    for (int i = tid; i < 128 * 8; i += 128) {
        int r = i >> 3, sg = i & 7;
        *(uint4*)&Bs[r][sg * 8] =
            *(const uint4*)&g_nh[((size_t)(b * SS + s0 + r)) * DD + h * HD + sg * 8];
    }
    __syncthreads();
    int nb = wid * 32;
    unsigned Bf[4][4][2];
#pragma unroll
    for (int j = 0; j < 4; j++)
#pragma unroll
        for (int kk = 0; kk < 4; kk++) {
            unsigned ad = su32(&Bs[nb + j * 8 + (lane & 7)][kk * 16 + (lane & 8)]);
            asm volatile("ldmatrix.sync.aligned.m8n8.x2.shared.b16 {%0,%1}, [%2];"
                : "=r"(Bf[j][kk][0]), "=r"(Bf[j][kk][1]) : "r"(ad));
        }
    __syncthreads();
#pragma unroll
    for (int mi = 0; mi < 4; mi++) {
        unsigned Af[4][4];
#pragma unroll
        for (int kk = 0; kk < 4; kk++) {
            unsigned ad = su32(&As[mi * 16 + (lane & 15)][kk * 16 + ((lane & 16) >> 1)]);
            asm volatile("ldmatrix.sync.aligned.m8n8.x4.shared.b16 {%0,%1,%2,%3}, [%4];"
                : "=r"(Af[kk][0]), "=r"(Af[kk][1]), "=r"(Af[kk][2]), "=r"(Af[kk][3])
                : "r"(ad));
        }
#pragma unroll
        for (int j = 0; j < 4; j++) {
            float c[4] = {0.f, 0.f, 0.f, 0.f};
#pragma unroll
            for (int kk = 0; kk < 4; kk++)
                MMA16816(c, Af[kk], Bf[j][kk][0], Bf[j][kk][1]);
            int m = mi * 16 + (lane >> 2);
            int n = nb + j * 8 + 2 * (lane & 3);
            *(__half2*)&Cs[m][n]     = __float22half2_rn(make_float2(c[0], c[1]));
            *(__half2*)&Cs[m + 8][n] = __float22half2_rn(make_float2(c[2], c[3]));
        }
    }
    __syncthreads();
    size_t lbase = (size_t)((b * HH + h) * MM) * SS + s0;
    for (int u = tid; u < 64 * 16; u += 128) {
        int m = u >> 4, q = u & 15;
        *(uint4*)&g_lh[lbase + (size_t)m * SS + q * 8] = *(const uint4*)&Cs[m][q * 8];
    }
}

// ---------------- K4: one-pass softmax stats -----------------------------------
__global__ void __launch_bounds__(128) k_stats() {
    int r = blockIdx.x, tid = threadIdx.x;
    const __half* row = g_lh + (size_t)r * SS;
    float4 raw[4];
    const float4* p = (const float4*)(row + tid * 32);
#pragma unroll
    for (int q = 0; q < 4; q++) raw[q] = p[q];
    float v[32];
#pragma unroll
    for (int q = 0; q < 4; q++) {
        const __half2* h2 = (const __half2*)&raw[q];
#pragma unroll
        for (int j = 0; j < 4; j++) {
            float2 f = __half22float2(h2[j]);
            v[q * 8 + j * 2] = f.x; v[q * 8 + j * 2 + 1] = f.y;
        }
    }
    float mx = -1e30f;
#pragma unroll
    for (int i = 0; i < 32; i++) mx = fmaxf(mx, v[i]);
    __shared__ float red[4];
    __shared__ float smxv;
    for (int o = 16; o; o >>= 1) mx = fmaxf(mx, __shfl_down_sync(~0u, mx, o));
    if ((tid & 31) == 0) red[tid >> 5] = mx;
    __syncthreads();
    if (tid == 0) smxv = fmaxf(fmaxf(red[0], red[1]), fmaxf(red[2], red[3]));
    __syncthreads();
    float gmx = smxv;
    float sm = 0.f;
#pragma unroll
    for (int i = 0; i < 32; i++) sm += __expf(v[i] - gmx);
    for (int o = 16; o; o >>= 1) sm += __shfl_down_sync(~0u, sm, o);
    __syncthreads();
    if ((tid & 31) == 0) red[tid >> 5] = sm;
    __syncthreads();
    if (tid == 0) {
        g_rmax[r] = gmx;
        g_rsum[r] = red[0] + red[1] + red[2] + red[3];
    }
}

// ---------------- K5: dispatch via mma --------------------------------------------
__global__ void __launch_bounds__(128) k_disp() {
    int ch = blockIdx.x, h = blockIdx.y, b = blockIdx.z;
    int tid = threadIdx.x, lane = tid & 31, wid = tid >> 5;
    __shared__ __half As[64][72];
    __shared__ __half Bs[64][72];
    __shared__ float smax[64], sinv[64], tns[512];
    if (tid < 64) {
        int r = (b * HH + h) * MM + tid;
        smax[tid] = g_rmax[r];
        sinv[tid] = 1.f / g_rsum[r];
    }
    for (int u = tid; u < 512; u += 128) tns[u] = g_tn[b * SS + ch * 512 + u];
    float acc[4][2][4];
#pragma unroll
    for (int i = 0; i < 4; i++)
#pragma unroll
        for (int j = 0; j < 2; j++)
#pragma unroll
            for (int q = 0; q < 4; q++) acc[i][j][q] = 0.f;
    size_t lbh = (size_t)((b * HH + h) * MM) * SS;
    int nb = wid * 16;
    __syncthreads();
    for (int tile = 0; tile < 8; tile++) {
        int s0 = ch * 512 + tile * 64;
        if (tile) __syncthreads();
        for (int u = tid; u < 512; u += 128) {
            int m = u >> 3, q = u & 7;
            uint4 raw = *(const uint4*)&g_lh[lbh + (size_t)m * SS + s0 + q * 8];
            const __half2* h2 = (const __half2*)&raw;
            float mm = smax[m], iv = sinv[m];
            const float* tp = &tns[tile * 64 + q * 8];
            __half2 outh[4];
#pragma unroll
            for (int j = 0; j < 4; j++) {
                float2 f = __half22float2(h2[j]);
                float e0 = __expf(f.x - mm) * iv * tp[2 * j];
                float e1 = __expf(f.y - mm) * iv * tp[2 * j + 1];
                outh[j] = __float22half2_rn(make_float2(e0, e1));
            }
            *(uint4*)&As[m][q * 8] = *(uint4*)outh;
        }
        for (int u = tid; u < 512; u += 128) {
            int s = u >> 3, q = u & 7;
            *(uint4*)&Bs[s][q * 8] =
                *(const uint4*)&g_nh[((size_t)(b * SS + s0 + s)) * DD + h * HD + q * 8];
        }
        __syncthreads();
#pragma unroll
        for (int kk = 0; kk < 4; kk++) {
            unsigned Af[4][4];
#pragma unroll
            for (int mi = 0; mi < 4; mi++) {
                unsigned ad = su32(&As[mi * 16 + (lane & 15)][kk * 16 + ((lane & 16) >> 1)]);
                asm volatile("ldmatrix.sync.aligned.m8n8.x4.shared.b16 {%0,%1,%2,%3}, [%4];"
                    : "=r"(Af[mi][0]), "=r"(Af[mi][1]), "=r"(Af[mi][2]), "=r"(Af[mi][3])
                    : "r"(ad));
            }
            unsigned Bf[4];
            {
                unsigned ad = su32(&Bs[kk * 16 + ((lane >> 3) & 1) * 8 + (lane & 7)]
                                     [nb + ((lane >> 4) & 1) * 8]);
                asm volatile("ldmatrix.sync.aligned.m8n8.x4.trans.shared.b16 {%0,%1,%2,%3}, [%4];"
                    : "=r"(Bf[0]), "=r"(Bf[1]), "=r"(Bf[2]), "=r"(Bf[3]) : "r"(ad));
            }
#pragma unroll
            for (int mi = 0; mi < 4; mi++) {
                MMA16816(acc[mi][0], Af[mi], Bf[0], Bf[1]);
                MMA16816(acc[mi][1], Af[mi], Bf[2], Bf[3]);
            }
        }
    }
#pragma unroll
    for (int mi = 0; mi < 4; mi++) {
        int m = mi * 16 + (lane >> 2);
#pragma unroll
        for (int nj = 0; nj < 2; nj++) {
            int d = nb + nj * 8 + 2 * (lane & 3);
            float* bp = &g_y[((size_t)(b * MM + m)) * DD + h * HD + d];
            atomicAdd(bp, acc[mi][nj][0]);
            atomicAdd(bp + 1, acc[mi][nj][1]);
            atomicAdd(bp + 8 * DD, acc[mi][nj][2]);
            atomicAdd(bp + 8 * DD + 1, acc[mi][nj][3]);
        }
    }
}

// ---------------- K6: fc1 (3-stage x 4-row cp.async ring, proven) --------------------
__global__ void __launch_bounds__(256) k_fc1(const float* __restrict__ w1) {
    int fblk = blockIdx.x, m = blockIdx.y, kc = blockIdx.z;
    int tid = threadIdx.x;
    int f = fblk * 1024 + tid * 4;
    __shared__ float ysT[128][12];
    __shared__ float wbuf[3][4][1024];
    for (int i = tid; i < 8 * 128; i += 256) {
        int bb = i >> 7, k = i & 127;
        ysT[k][bb] = g_y[((size_t)(bb * MM + m)) * DD + kc * 128 + k];
    }
    __syncthreads();
    const float* wp = w1 + (size_t)m * DD * FF + (size_t)(kc * 128) * FF + f;
    const int NS = 32;
#pragma unroll
    for (int s = 0; s < 2; s++) {
#pragma unroll
        for (int j = 0; j < 4; j++)
            cpasync16(su32(&wbuf[s][j][tid * 4]), wp + (size_t)(s * 4 + j) * FF);
        asm volatile("cp.async.commit_group;");
    }
    ull acc[4][4];
#pragma unroll
    for (int i = 0; i < 4; i++)
#pragma unroll
        for (int j = 0; j < 4; j++) acc[i][j] = 0ull;
    int nxt = 2;
    for (int s = 0; s < NS; s++) {
        int buf = s % 3;
        if (s + 2 < NS) {
            int nb2 = nxt; nxt = (nxt + 1) % 3;
#pragma unroll
            for (int j = 0; j < 4; j++)
                cpasync16(su32(&wbuf[nb2][j][tid * 4]), wp + (size_t)((s + 2) * 4 + j) * FF);
            asm volatile("cp.async.commit_group;");
            asm volatile("cp.async.wait_group 2;");
        } else if (s + 1 < NS) {
            asm volatile("cp.async.wait_group 1;");
        } else {
            asm volatile("cp.async.wait_group 0;");
        }
#pragma unroll
        for (int j = 0; j < 4; j++) {
            int k = s * 4 + j;
            float4 wv = *(const float4*)&wbuf[buf][j][tid * 4];
            ulonglong2 ya = *(const ulonglong2*)&ysT[k][0];
            ulonglong2 yb = *(const ulonglong2*)&ysT[k][4];
            ull d0 = pk2(wv.x, wv.x), d1 = pk2(wv.y, wv.y);
            ull d2 = pk2(wv.z, wv.z), d3 = pk2(wv.w, wv.w);
            FMA2(acc[0][0], d0, ya.x); FMA2(acc[0][1], d0, ya.y); FMA2(acc[0][2], d0, yb.x); FMA2(acc[0][3], d0, yb.y);
            FMA2(acc[1][0], d1, ya.x); FMA2(acc[1][1], d1, ya.y); FMA2(acc[1][2], d1, yb.x); FMA2(acc[1][3], d1, yb.y);
            FMA2(acc[2][0], d2, ya.x); FMA2(acc[2][1], d2, ya.y); FMA2(acc[2][2], d2, yb.x); FMA2(acc[2][3], d2, yb.y);
            FMA2(acc[3][0], d3, ya.x); FMA2(acc[3][1], d3, ya.y); FMA2(acc[3][2], d3, yb.x); FMA2(acc[3][3], d3, yb.y);
        }
    }
#pragma unroll
    for (int fi = 0; fi < 4; fi++)
#pragma unroll
        for (int bp = 0; bp < 4; bp++) {
            float a0, a1;
            upk2(acc[fi][bp], a0, a1);
            atomicAdd(&g_hid[((size_t)((2 * bp) * MM + m)) * FF + f + fi], a0);
            atomicAdd(&g_hid[((size_t)((2 * bp + 1) * MM + m)) * FF + f + fi], a1);
        }
}

// ---------------- K7: fc2 (gelu on load; 3-stage x 4-row cp.async ring, proven) ------
__global__ void __launch_bounds__(192) k_fc2(const float* __restrict__ w2) {
    int m = blockIdx.x, kc = blockIdx.y;
    int tid = threadIdx.x;
    int d = tid * 4;
    __shared__ float hsT[192][12];
    __shared__ float wbuf[3][4][768];
    for (int i = tid; i < 8 * 192; i += 192) {
        int bb = i / 192, k = i % 192;
        float v = g_hid[((size_t)(bb * MM + m)) * FF + kc * 192 + k];
        hsT[k][bb] = 0.5f * v * (1.f + erff(v * 0.70710678118654752f));
    }
    __syncthreads();
    const float* wp = w2 + (size_t)m * FF * DD + (size_t)(kc * 192) * DD + d;
    const int NS = 48;
#pragma unroll
    for (int s = 0; s < 2; s++) {
#pragma unroll
        for (int j = 0; j < 4; j++)
            cpasync16(su32(&wbuf[s][j][tid * 4]), wp + (size_t)(s * 4 + j) * DD);
        asm volatile("cp.async.commit_group;");
    }
    ull acc[4][4];
#pragma unroll
    for (int i = 0; i < 4; i++)
#pragma unroll
        for (int j = 0; j < 4; j++) acc[i][j] = 0ull;
    int nxt = 2;
    for (int s = 0; s < NS; s++) {
        int buf = s % 3;
        if (s + 2 < NS) {
            int nb2 = nxt; nxt = (nxt + 1) % 3;
#pragma unroll
            for (int j = 0; j < 4; j++)
                cpasync16(su32(&wbuf[nb2][j][tid * 4]), wp + (size_t)((s + 2) * 4 + j) * DD);
            asm volatile("cp.async.commit_group;");
            asm volatile("cp.async.wait_group 2;");
        } else if (s + 1 < NS) {
            asm volatile("cp.async.wait_group 1;");
        } else {
            asm volatile("cp.async.wait_group 0;");
        }
#pragma unroll
        for (int j = 0; j < 4; j++) {
            int k = s * 4 + j;
            float4 wv = *(const float4*)&wbuf[buf][j][tid * 4];
            ulonglong2 ya = *(const ulonglong2*)&hsT[k][0];
            ulonglong2 yb = *(const ulonglong2*)&hsT[k][4];
            ull d0 = pk2(wv.x, wv.x), d1 = pk2(wv.y, wv.y);
            ull d2 = pk2(wv.z, wv.z), d3 = pk2(wv.w, wv.w);
            FMA2(acc[0][0], d0, ya.x); FMA2(acc[0][1], d0, ya.y); FMA2(acc[0][2], d0, yb.x); FMA2(acc[0][3], d0, yb.y);
            FMA2(acc[1][0], d1, ya.x); FMA2(acc[1][1], d1, ya.y); FMA2(acc[1][2], d1, yb.x); FMA2(acc[1][3], d1, yb.y);
            FMA2(acc[2][0], d2, ya.x); FMA2(acc[2][1], d2, ya.y); FMA2(acc[2][2], d2, yb.x); FMA2(acc[2][3], d2, yb.y);
            FMA2(acc[3][0], d3, ya.x); FMA2(acc[3][1], d3, ya.y); FMA2(acc[3][2], d3, yb.x); FMA2(acc[3][3], d3, yb.y);
        }
    }
#pragma unroll
    for (int di = 0; di < 4; di++)
#pragma unroll
        for (int bp = 0; bp < 4; bp++) {
            float a0, a1;
            upk2(acc[di][bp], a0, a1);
            atomicAdd(&g_y2[((size_t)((2 * bp) * MM + m)) * DD + d + di], a0);
            atomicAdd(&g_y2[((size_t)((2 * bp + 1) * MM + m)) * DD + d + di], a1);
        }
}

// ---------------- K8: combine via mma -----------------------------------------------
__global__ void __launch_bounds__(128) k_comb(float* __restrict__ out) {
    int sb = blockIdx.x, h = blockIdx.y, b = blockIdx.z;
    int s0 = sb * 128;
    int tid = threadIdx.x, lane = tid & 31, w = tid >> 5;
    __shared__ __half As[64][136];
    __shared__ __half Bs[64][72];
    __shared__ float sinvs[128];
    size_t lbh = (size_t)((b * HH + h) * MM) * SS;
    for (int u = tid; u < 1024; u += 128) {
        int m = u >> 4, q = u & 15;
        *(uint4*)&As[m][q * 8] = *(const uint4*)&g_lh[lbh + (size_t)m * SS + s0 + q * 8];
    }
    for (int u = tid; u < 1024; u += 128) {
        int m = u >> 4, q = u & 15;
        float4 v = *(const float4*)&g_y2[((size_t)(b * MM + m)) * DD + h * HD + q * 4];
        __half2 h0 = __float22half2_rn(make_float2(v.x, v.y));
        __half2 h1 = __float22half2_rn(make_float2(v.z, v.w));
        uint2 st;
        st.x = *(unsigned*)&h0; st.y = *(unsigned*)&h1;
        *(uint2*)&Bs[m][q * 4] = st;
    }
    __syncthreads();
    {
        float vals[64];
        float mx = -1e30f;
#pragma unroll
        for (int m = 0; m < 64; m++) {
            vals[m] = __half2float(As[m][tid]);
            mx = fmaxf(mx, vals[m]);
        }
        float sm = 0.f;
#pragma unroll
        for (int m = 0; m < 64; m++) {
            float e = __expf(vals[m] - mx);
            sm += e;
            As[m][tid] = __float2half(e);
        }
        sinvs[tid] = 1.f / sm;
    }
    __syncthreads();
    float acc[2][8][4];
#pragma unroll
    for (int i = 0; i < 2; i++)
#pragma unroll
        for (int j = 0; j < 8; j++)
#pragma unroll
            for (int q = 0; q < 4; q++) acc[i][j][q] = 0.f;
#pragma unroll
    for (int kk = 0; kk < 4; kk++) {
        unsigned Af[2][4];
#pragma unroll
        for (int mi2 = 0; mi2 < 2; mi2++) {
            int M0 = w * 32 + mi2 * 16;
            unsigned ad = su32(&As[kk * 16 + ((lane >> 4) & 1) * 8 + (lane & 7)]
                                 [M0 + ((lane >> 3) & 1) * 8]);
            asm volatile("ldmatrix.sync.aligned.m8n8.x4.trans.shared.b16 {%0,%1,%2,%3}, [%4];"
                : "=r"(Af[mi2][0]), "=r"(Af[mi2][1]), "=r"(Af[mi2][2]), "=r"(Af[mi2][3])
                : "r"(ad));
        }
        unsigned Bf[4][4];
#pragma unroll
        for (int p = 0; p < 4; p++) {
            unsigned ad = su32(&Bs[kk * 16 + ((lane >> 3) & 1) * 8 + (lane & 7)]
                                 [p * 16 + ((lane >> 4) & 1) * 8]);
            asm volatile("ldmatrix.sync.aligned.m8n8.x4.trans.shared.b16 {%0,%1,%2,%3}, [%4];"
                : "=r"(Bf[p][0]), "=r"(Bf[p][1]), "=r"(Bf[p][2]), "=r"(Bf[p][3])
                : "r"(ad));
        }
#pragma unroll
        for (int mi2 = 0; mi2 < 2; mi2++)
#pragma unroll
            for (int nj = 0; nj < 8; nj++)
                MMA16816(acc[mi2][nj], Af[mi2], Bf[nj >> 1][(nj & 1) * 2], Bf[nj >> 1][(nj & 1) * 2 + 1]);
    }
#pragma unroll
    for (int mi2 = 0; mi2 < 2; mi2++) {
        int srow = w * 32 + mi2 * 16 + (lane >> 2);
        float inv0 = sinvs[srow], inv1 = sinvs[srow + 8];
        float* o0 = &out[((size_t)(b * SS + s0 + srow)) * DD + h * HD];
        float* o1 = o0 + (size_t)8 * DD;
#pragma unroll
        for (int nj = 0; nj < 8; nj++) {
            int d = nj * 8 + 2 * (lane & 3);
            float2 v0 = make_float2(acc[mi2][nj][0] * inv0, acc[mi2][nj][1] * inv0);
            float2 v1 = make_float2(acc[mi2][nj][2] * inv1, acc[mi2][nj][3] * inv1);
            *(float2*)&o0[d] = v0;
            *(float2*)&o1[d] = v1;
        }
    }
}

// ---------------- launch --------------------------------------------------------
extern "C" void kernel_launch(void* const* d_in, const int* in_sizes, int n_in,
                              void* d_out, int out_size) {
    const float* x      = (const float*)d_in[0];
    const float* slots  = (const float*)d_in[1];
    const float* scale  = (const float*)d_in[2];
    const float* fc1_w  = (const float*)d_in[3];
    const float* fc1_b  = (const float*)d_in[4];
    const float* fc2_w  = (const float*)d_in[5];
    const float* fc2_b  = (const float*)d_in[6];
    const float* norm_w = (const float*)d_in[7];
    float* out = (float*)d_out;

    k_slots<<<MM, 256>>>(slots, scale);                                    // idx 0
    k_norm<<<BB * SS / 8, 256>>>(x, norm_w);                               // idx 1
    k_binit<<<(BB * MM * (2 * DD + FF)) / 1024, 256>>>(fc1_b, fc2_b);      // idx 2
    k_logits<<<dim3(SS / 128, HH, BB), 128>>>();                           // idx 3 (profiled)
    k_stats<<<BB * HH * MM, 128>>>();                                      // idx 4
    k_disp<<<dim3(8, HH, BB), 128>>>();                                    // idx 5
    k_fc1<<<dim3(3, MM, 6), 256>>>(fc1_w);                                 // idx 6
    k_fc2<<<dim3(MM, 16), 192>>>(fc2_w);                                   // idx 7
    k_comb<<<dim3(SS / 128, HH, BB), 128>>>(out);                          // idx 8
}